// round 7
// baseline (speedup 1.0000x reference)
#include <cuda_runtime.h>
#include <cuda_fp16.h>
#include <math.h>
#include <stdint.h>

#define CEMB 1024
#define NHEADS 16
#define HS 64
#define DFF 4096
#define BB 4
#define TT 2048
#define MROWS (BB*TT)   // 8192

#define BM 128
#define BN 128
#define BKE 64
#define GT 256

// ---------------- scratch ----------------
__device__ float g_x2 [(size_t)MROWS * CEMB];
__device__ __half g_h [(size_t)MROWS * CEMB];       // ln out
__device__ __half g_y [(size_t)MROWS * CEMB];       // attn out
__device__ __half g_f [(size_t)MROWS * DFF];        // mlp hidden
// weights, transposed to [N,K] K-major, fp16
__device__ __half g_wa[(size_t)3*CEMB * CEMB];
__device__ __half g_wp[(size_t)CEMB * CEMB];
__device__ __half g_wf[(size_t)DFF * CEMB];
__device__ __half g_w2[(size_t)CEMB * DFF];
// attention operands [bh][t][d], q pre-scaled by 0.125
__device__ __half g_aq[(size_t)64 * TT * HS];
__device__ __half g_ak[(size_t)64 * TT * HS];
__device__ __half g_av[(size_t)64 * TT * HS];

// ---------------- PTX helpers ----------------
__device__ __forceinline__ uint32_t smem_u32(const void* p) {
    uint32_t a;
    asm("{ .reg .u64 t; cvta.to.shared.u64 t, %1; cvt.u32.u64 %0, t; }" : "=r"(a) : "l"(p));
    return a;
}
#define CP_ASYNC16(s, g) \
    asm volatile("cp.async.cg.shared.global [%0], [%1], 16;" :: "r"(s), "l"(g) : "memory")
#define CP_COMMIT() asm volatile("cp.async.commit_group;" ::: "memory")
#define CP_WAIT1()  asm volatile("cp.async.wait_group 1;" ::: "memory")
#define CP_WAIT0()  asm volatile("cp.async.wait_group 0;" ::: "memory")
#define LDSM_X4(r0, r1, r2, r3, addr) \
    asm volatile("ldmatrix.sync.aligned.m8n8.x4.shared.b16 {%0,%1,%2,%3}, [%4];" \
        : "=r"(r0), "=r"(r1), "=r"(r2), "=r"(r3) : "r"(addr))
#define LDSM_X4_T(r0, r1, r2, r3, addr) \
    asm volatile("ldmatrix.sync.aligned.m8n8.x4.trans.shared.b16 {%0,%1,%2,%3}, [%4];" \
        : "=r"(r0), "=r"(r1), "=r"(r2), "=r"(r3) : "r"(addr))
#define MMAF16(c, a, b0v, b1v) \
    asm volatile("mma.sync.aligned.m16n8k16.row.col.f32.f16.f16.f32 " \
        "{%0,%1,%2,%3}, {%4,%5,%6,%7}, {%8,%9}, {%0,%1,%2,%3};" \
        : "+f"((c)[0]), "+f"((c)[1]), "+f"((c)[2]), "+f"((c)[3]) \
        : "r"((a)[0]), "r"((a)[1]), "r"((a)[2]), "r"((a)[3]), "r"(b0v), "r"(b1v))
#define STS32(addr, v) \
    asm volatile("st.shared.b32 [%0], %1;" :: "r"(addr), "r"(v) : "memory")
#define LDS128(r0, r1, r2, r3, addr) \
    asm volatile("ld.shared.v4.b32 {%0,%1,%2,%3}, [%4];" \
        : "=r"(r0), "=r"(r1), "=r"(r2), "=r"(r3) : "r"(addr))

__device__ __forceinline__ uint32_t sw128(uint32_t off) { return off ^ ((off >> 3) & 0x70); }

__device__ __forceinline__ float gelu_f(float x) {
    float t = tanhf(0.79788456080286536f * (x + 0.044715f * x * x * x));
    return 0.5f * x * (1.0f + t);
}

union H4 { __half h[4]; uint2 u; };
union H2 { __half h[2]; uint32_t u; };

// ---------------- weight transpose + fp16 convert ----------------
__global__ __launch_bounds__(256) void wconv_kernel(const float* __restrict__ W,
    __half* __restrict__ Wf, int K, int N)
{
    __shared__ float t[32][33];
    int n0 = blockIdx.x * 32, k0 = blockIdx.y * 32;
    int tx = threadIdx.x & 31, ty = threadIdx.x >> 5;
    #pragma unroll
    for (int r = ty; r < 32; r += 8)
        t[r][tx] = W[(size_t)(k0 + r) * N + n0 + tx];
    __syncthreads();
    #pragma unroll
    for (int r = ty; r < 32; r += 8)
        Wf[(size_t)(n0 + r) * K + k0 + tx] = __float2half(t[tx][r]);
}

// ---------------- LayerNorm -> fp16 ----------------
__global__ __launch_bounds__(256) void ln_kernel(const float* __restrict__ x,
                                                 const float* __restrict__ g,
                                                 const float* __restrict__ b,
                                                 __half* __restrict__ oh)
{
    int row = blockIdx.x;
    int t = threadIdx.x;
    float4 v = ((const float4*)(x + (size_t)row * CEMB))[t];
    float s  = v.x + v.y + v.z + v.w;
    float ss = v.x*v.x + v.y*v.y + v.z*v.z + v.w*v.w;
    #pragma unroll
    for (int o = 16; o > 0; o >>= 1) {
        s  += __shfl_xor_sync(0xffffffffu, s,  o);
        ss += __shfl_xor_sync(0xffffffffu, ss, o);
    }
    __shared__ float red[16];
    int warp = t >> 5, lane = t & 31;
    if (lane == 0) { red[warp] = s; red[warp + 8] = ss; }
    __syncthreads();
    float sum = 0.f, sumsq = 0.f;
    #pragma unroll
    for (int w = 0; w < 8; w++) { sum += red[w]; sumsq += red[w + 8]; }
    float mu   = sum * (1.0f / CEMB);
    float var  = sumsq * (1.0f / CEMB) - mu * mu;
    float rstd = rsqrtf(var + 1e-5f);
    float4 gv = ((const float4*)g)[t];
    float4 bv = ((const float4*)b)[t];
    H4 o;
    o.h[0] = __float2half((v.x - mu) * rstd * gv.x + bv.x);
    o.h[1] = __float2half((v.y - mu) * rstd * gv.y + bv.y);
    o.h[2] = __float2half((v.z - mu) * rstd * gv.z + bv.z);
    o.h[3] = __float2half((v.w - mu) * rstd * gv.w + bv.w);
    *(uint2*)(oh + (size_t)row * CEMB + t * 4) = o.u;
}

// ---------------- HMMA fp16 GEMM: C = A @ B^T + bias ----------------
// EPI: 1 = fp32 out + residual, 2 = gelu -> fp16, 3 = fused QKV scatter (fp16 Q/K/V)
// stage: A 16K | B 16K = 32KB, double buffered -> 64KB, 2 CTAs/SM.
#define STAGE_BYTES 32768
#define SMEM_GEMM (2 * STAGE_BYTES + 1024)

template<int EPI>
__global__ __launch_bounds__(GT, 2) void gemm_f16(
    const __half* __restrict__ Ah,
    const __half* __restrict__ Bf,
    const float* __restrict__ bias, const float* __restrict__ R,
    float* __restrict__ Cf, __half* __restrict__ Ch,
    __half* __restrict__ Cq, __half* __restrict__ Ck, __half* __restrict__ Cv,
    int M, int N, int K)
{
    extern __shared__ char dsm[];
    uintptr_t pa = ((uintptr_t)dsm + 1023) & ~(uintptr_t)1023;
    uint32_t sb = smem_u32((char*)pa);

    int tid = threadIdx.x;
    int wid = tid >> 5, lid = tid & 31;
    int wm = wid >> 1, wn = wid & 1;
    int m0 = blockIdx.y * BM, n0 = blockIdx.x * BN;

    const int NC = K / BKE;
    int lrow = tid >> 3;
    int lch  = tid & 7;

    auto load_stage = [&](int c) {
        int buf = c & 1;
        uint32_t st = sb + buf * STAGE_BYTES;
        int k0 = c * BKE;
        #pragma unroll
        for (int t = 0; t < 4; t++) {
            int row = lrow + t * 32;
            uint32_t so = sw128((uint32_t)(row * 128 + lch * 16));
            size_t ga = (size_t)(m0 + row) * K + k0 + lch * 8;
            CP_ASYNC16(st + so,         (const char*)(Ah + ga));
            size_t gb = (size_t)(n0 + row) * K + k0 + lch * 8;
            CP_ASYNC16(st + 16384 + so, (const char*)(Bf + gb));
        }
    };

    float acc[2][8][4];
    #pragma unroll
    for (int mi = 0; mi < 2; mi++)
        #pragma unroll
        for (int j = 0; j < 8; j++)
            #pragma unroll
            for (int q = 0; q < 4; q++) acc[mi][j][q] = 0.f;

    int lrow16 = lid & 15;
    int khalf  = lid >> 4;

    load_stage(0);
    CP_COMMIT();

    for (int c = 0; c < NC; c++) {
        if (c + 1 < NC) { load_stage(c + 1); CP_COMMIT(); CP_WAIT1(); }
        else            { CP_WAIT0(); }
        __syncthreads();

        uint32_t st = sb + (c & 1) * STAGE_BYTES;

        #pragma unroll
        for (int s = 0; s < 4; s++) {
            uint32_t aH[2][4], bH[4][4];
            #pragma unroll
            for (int mi = 0; mi < 2; mi++) {
                int row = wm * 32 + mi * 16 + lrow16;
                int ch = (s * 2 + khalf) ^ (row & 7);
                uint32_t ad = st + (uint32_t)(row * 128 + ch * 16);
                LDSM_X4(aH[mi][0], aH[mi][1], aH[mi][2], aH[mi][3], ad);
            }
            #pragma unroll
            for (int nb = 0; nb < 4; nb++) {
                int row = wn * 64 + nb * 16 + lrow16;
                int ch = (s * 2 + khalf) ^ (row & 7);
                uint32_t bd = st + 16384 + (uint32_t)(row * 128 + ch * 16);
                LDSM_X4(bH[nb][0], bH[nb][1], bH[nb][2], bH[nb][3], bd);
            }
            #pragma unroll
            for (int mi = 0; mi < 2; mi++) {
                #pragma unroll
                for (int nb = 0; nb < 4; nb++) {
                    MMAF16(acc[mi][nb*2],   aH[mi], bH[nb][0], bH[nb][2]);
                    MMAF16(acc[mi][nb*2+1], aH[mi], bH[nb][1], bH[nb][3]);
                }
            }
        }
        __syncthreads();
    }

    int gid = lid >> 2, tig = lid & 3;

    if (EPI == 3) {
        // --- fused QKV epilogue: stage fp16 tile, then coalesced scatter ---
        // stage layout: 128 rows x 256B, padded stride 272B (bank-conflict-free)
        #pragma unroll
        for (int mi = 0; mi < 2; mi++) {
            #pragma unroll
            for (int j = 0; j < 8; j++) {
                int lr = wm * 32 + mi * 16 + gid;
                int lc = wn * 64 + j * 8 + tig * 2;
                int col = n0 + lc;
                float b0 = bias[col], b1 = bias[col + 1];
                float sc = (col < CEMB) ? 0.125f : 1.0f;
                H2 h;
                h.h[0] = __float2half((acc[mi][j][0] + b0) * sc);
                h.h[1] = __float2half((acc[mi][j][1] + b1) * sc);
                STS32(sb + (uint32_t)(lr * 272 + lc * 2), h.u);
                h.h[0] = __float2half((acc[mi][j][2] + b0) * sc);
                h.h[1] = __float2half((acc[mi][j][3] + b1) * sc);
                STS32(sb + (uint32_t)((lr + 8) * 272 + lc * 2), h.u);
            }
        }
        __syncthreads();
        #pragma unroll
        for (int k = 0; k < 8; k++) {
            int unit = tid + k * 256;        // 2048 units of 16B
            int seg  = unit >> 3;            // 256 segments (row, head-half)
            int off  = (unit & 7) * 16;      // byte offset within 128B
            int lrw  = seg >> 1;
            int hseg = seg & 1;
            int gcol = n0 + hseg * 64;
            int which = gcol >> 10;
            int hd = (gcol >> 6) & 15;
            int grow = m0 + lrw;
            int bb = grow >> 11, tt2 = grow & (TT - 1);
            uint32_t r0v, r1v, r2v, r3v;
            LDS128(r0v, r1v, r2v, r3v, sb + (uint32_t)(lrw * 272 + hseg * 128 + off));
            __half* dst = (which == 0) ? Cq : (which == 1) ? Ck : Cv;
            *(uint4*)(dst + ((size_t)(bb * 16 + hd) * TT + tt2) * HS + (off >> 1)) =
                make_uint4(r0v, r1v, r2v, r3v);
        }
        return;
    }

    #pragma unroll
    for (int mi = 0; mi < 2; mi++) {
        #pragma unroll
        for (int j = 0; j < 8; j++) {
            int r0 = m0 + wm * 32 + mi * 16 + gid;
            int r1 = r0 + 8;
            int col = n0 + wn * 64 + j * 8 + tig * 2;
            float b0 = bias[col], b1 = bias[col + 1];
            float v0 = acc[mi][j][0] + b0, v1 = acc[mi][j][1] + b1;
            float v2 = acc[mi][j][2] + b0, v3 = acc[mi][j][3] + b1;
            if (EPI == 1) {
                float2 q0 = *(const float2*)(R + (size_t)r0 * N + col);
                float2 q1 = *(const float2*)(R + (size_t)r1 * N + col);
                v0 += q0.x; v1 += q0.y; v2 += q1.x; v3 += q1.y;
            }
            if (EPI == 2) {
                v0 = gelu_f(v0); v1 = gelu_f(v1); v2 = gelu_f(v2); v3 = gelu_f(v3);
                H2 h0, h1;
                h0.h[0] = __float2half(v0); h0.h[1] = __float2half(v1);
                h1.h[0] = __float2half(v2); h1.h[1] = __float2half(v3);
                *(uint32_t*)(Ch + (size_t)r0 * N + col) = h0.u;
                *(uint32_t*)(Ch + (size_t)r1 * N + col) = h1.u;
            } else {
                *(float2*)(Cf + (size_t)r0 * N + col) = make_float2(v0, v1);
                *(float2*)(Cf + (size_t)r1 * N + col) = make_float2(v2, v3);
            }
        }
    }
}

// ---------------- HMMA flash attention (all fp16, V via ldmatrix.trans) ----------------
// smem: Q 16K @0 | buf(b) @16K+16K*b: K 8K, V 8K | P 16K @48K = 64KB
#define ATSM_BUF(b) (16384 + (b) * 16384)
#define ATSM_P 49152
#define ATT_SMEM (65536 + 1024)

__global__ __launch_bounds__(256, 2) void attn_mma_kernel(
    const __half* __restrict__ Qf_, const __half* __restrict__ Kf_,
    const __half* __restrict__ Vf_,
    __half* __restrict__ yo)
{
    extern __shared__ char dsm[];
    uintptr_t pa = ((uintptr_t)dsm + 1023) & ~(uintptr_t)1023;
    uint32_t sb = smem_u32((char*)pa);

    int qt = gridDim.x - 1 - blockIdx.x;
    int q0 = qt * 128;
    int bh = blockIdx.y;
    int b = bh >> 4, hd = bh & 15;
    size_t hq = (size_t)bh * TT * HS;

    int tid = threadIdx.x;
    int wid = tid >> 5, lid = tid & 31;
    int lrow16 = lid & 15, khalf = lid >> 4;
    int arow = wid * 16 + lrow16;
    // lane geometry for trans B loads (V)
    int vrow_in = (lid & 7) + ((lid >> 4) << 3);   // t-row within 16
    int vhalf   = (lid >> 3) & 1;                  // d-chunk half

    auto load_kv = [&](int jb, int buf) {
        int j0 = jb * 64;
        uint32_t st = sb + ATSM_BUF(buf);
        const char* kf = (const char*)(Kf_ + hq + (size_t)j0 * HS);
        const char* vf = (const char*)(Vf_ + hq + (size_t)j0 * HS);
        #pragma unroll
        for (int i = tid; i < 512; i += 256) {
            int row = i >> 3, ch = i & 7;
            uint32_t so = sw128((uint32_t)(row * 128 + ch * 16));
            CP_ASYNC16(st + so,        kf + row * 128 + ch * 16);
            CP_ASYNC16(st + 8192 + so, vf + row * 128 + ch * 16);
        }
    };

    {
        const char* qf = (const char*)(Qf_ + hq + (size_t)q0 * HS);
        #pragma unroll
        for (int i = tid; i < 1024; i += 256) {
            int row = i >> 3, ch = i & 7;
            uint32_t so = sw128((uint32_t)(row * 128 + ch * 16));
            CP_ASYNC16(sb + so, qf + row * 128 + ch * 16);
        }
    }
    load_kv(0, 0);
    CP_COMMIT();

    float m_[2] = {-INFINITY, -INFINITY};
    float l_[2] = {0.f, 0.f};
    float acc[8][4];
    #pragma unroll
    for (int nb = 0; nb < 8; nb++)
        #pragma unroll
        for (int q = 0; q < 4; q++) acc[nb][q] = 0.f;

    int jbmax = q0 / 64 + 1;
    for (int jb = 0; jb <= jbmax; jb++) {
        int buf = jb & 1;
        CP_WAIT0();
        __syncthreads();
        if (jb < jbmax) { load_kv(jb + 1, buf ^ 1); CP_COMMIT(); }

        uint32_t sK = sb + ATSM_BUF(buf);
        uint32_t sV = sK + 8192;

        float s[8][4];
        #pragma unroll
        for (int nb = 0; nb < 8; nb++)
            #pragma unroll
            for (int q = 0; q < 4; q++) s[nb][q] = 0.f;

        #pragma unroll
        for (int ks = 0; ks < 4; ks++) {
            int ach = (ks * 2 + khalf) ^ (arow & 7);
            uint32_t aa = sb + (uint32_t)(arow * 128 + ach * 16);
            uint32_t aH[4];
            LDSM_X4(aH[0], aH[1], aH[2], aH[3], aa);
            uint32_t bH[4][4];
            #pragma unroll
            for (int nb2 = 0; nb2 < 4; nb2++) {
                int br = nb2 * 16 + lrow16;
                int bch = (ks * 2 + khalf) ^ (br & 7);
                uint32_t ba = sK + (uint32_t)(br * 128 + bch * 16);
                LDSM_X4(bH[nb2][0], bH[nb2][1], bH[nb2][2], bH[nb2][3], ba);
            }
            #pragma unroll
            for (int nb2 = 0; nb2 < 4; nb2++) {
                MMAF16(s[nb2*2],   aH, bH[nb2][0], bH[nb2][2]);
                MMAF16(s[nb2*2+1], aH, bH[nb2][1], bH[nb2][3]);
            }
        }

        int j0 = jb * 64;
        if (j0 + 63 > q0 + wid * 16) {
            int r0g = q0 + wid * 16 + (lid >> 2);
            #pragma unroll
            for (int nb = 0; nb < 8; nb++) {
                int c0 = j0 + nb * 8 + (lid & 3) * 2;
                if (c0     > r0g)     s[nb][0] = -INFINITY;
                if (c0 + 1 > r0g)     s[nb][1] = -INFINITY;
                if (c0     > r0g + 8) s[nb][2] = -INFINITY;
                if (c0 + 1 > r0g + 8) s[nb][3] = -INFINITY;
            }
        }

        float rmax[2] = {-INFINITY, -INFINITY};
        #pragma unroll
        for (int nb = 0; nb < 8; nb++) {
            rmax[0] = fmaxf(rmax[0], fmaxf(s[nb][0], s[nb][1]));
            rmax[1] = fmaxf(rmax[1], fmaxf(s[nb][2], s[nb][3]));
        }
        #pragma unroll
        for (int o = 1; o <= 2; o <<= 1) {
            rmax[0] = fmaxf(rmax[0], __shfl_xor_sync(0xffffffffu, rmax[0], o));
            rmax[1] = fmaxf(rmax[1], __shfl_xor_sync(0xffffffffu, rmax[1], o));
        }
        float mn0 = fmaxf(m_[0], rmax[0]);
        float mn1 = fmaxf(m_[1], rmax[1]);
        float alpha0 = __expf(m_[0] - mn0);
        float alpha1 = __expf(m_[1] - mn1);
        m_[0] = mn0; m_[1] = mn1;
        float rs[2] = {0.f, 0.f};
        #pragma unroll
        for (int nb = 0; nb < 8; nb++) {
            s[nb][0] = __expf(s[nb][0] - mn0); rs[0] += s[nb][0];
            s[nb][1] = __expf(s[nb][1] - mn0); rs[0] += s[nb][1];
            s[nb][2] = __expf(s[nb][2] - mn1); rs[1] += s[nb][2];
            s[nb][3] = __expf(s[nb][3] - mn1); rs[1] += s[nb][3];
        }
        #pragma unroll
        for (int o = 1; o <= 2; o <<= 1) {
            rs[0] += __shfl_xor_sync(0xffffffffu, rs[0], o);
            rs[1] += __shfl_xor_sync(0xffffffffu, rs[1], o);
        }
        l_[0] = l_[0] * alpha0 + rs[0];
        l_[1] = l_[1] * alpha1 + rs[1];
        #pragma unroll
        for (int nb = 0; nb < 8; nb++) {
            acc[nb][0] *= alpha0; acc[nb][1] *= alpha0;
            acc[nb][2] *= alpha1; acc[nb][3] *= alpha1;
        }

        {
            int r0 = wid * 16 + (lid >> 2);
            #pragma unroll
            for (int nb = 0; nb < 8; nb++) {
                int coff = (nb * 8 + (lid & 3) * 2) * 2;
                uint32_t o0 = sw128((uint32_t)(r0 * 128 + coff));
                uint32_t o1 = sw128((uint32_t)((r0 + 8) * 128 + coff));
                H2 h;
                h.h[0] = __float2half(s[nb][0]); h.h[1] = __float2half(s[nb][1]);
                STS32(sb + ATSM_P + o0, h.u);
                h.h[0] = __float2half(s[nb][2]); h.h[1] = __float2half(s[nb][3]);
                STS32(sb + ATSM_P + o1, h.u);
            }
        }
        __syncwarp();

        #pragma unroll
        for (int ks = 0; ks < 4; ks++) {
            int ach = (ks * 2 + khalf) ^ (arow & 7);
            uint32_t paddr = sb + ATSM_P + (uint32_t)(arow * 128 + ach * 16);
            uint32_t pH[4];
            LDSM_X4(pH[0], pH[1], pH[2], pH[3], paddr);
            uint32_t bH[4][4];
            int trow = ks * 16 + vrow_in;
            #pragma unroll
            for (int nb2 = 0; nb2 < 4; nb2++) {
                int chunk = nb2 * 2 + vhalf;
                uint32_t ba = sV + (uint32_t)(trow * 128 + ((chunk ^ (trow & 7)) * 16));
                LDSM_X4_T(bH[nb2][0], bH[nb2][1], bH[nb2][2], bH[nb2][3], ba);
            }
            #pragma unroll
            for (int nb2 = 0; nb2 < 4; nb2++) {
                MMAF16(acc[nb2*2],   pH, bH[nb2][0], bH[nb2][2]);
                MMAF16(acc[nb2*2+1], pH, bH[nb2][1], bH[nb2][3]);
            }
        }
    }

    float inv0 = 1.0f / l_[0];
    float inv1 = 1.0f / l_[1];
    size_t r0g = (size_t)b * TT + q0 + wid * 16 + (lid >> 2);
    #pragma unroll
    for (int nb = 0; nb < 8; nb++) {
        int col = hd * HS + nb * 8 + (lid & 3) * 2;
        H2 h;
        h.h[0] = __float2half(acc[nb][0] * inv0);
        h.h[1] = __float2half(acc[nb][1] * inv0);
        *(uint32_t*)(yo + r0g * CEMB + col) = h.u;
        h.h[0] = __float2half(acc[nb][2] * inv1);
        h.h[1] = __float2half(acc[nb][3] * inv1);
        *(uint32_t*)(yo + (r0g + 8) * CEMB + col) = h.u;
    }
}

// ---------------- launch ----------------
extern "C" void kernel_launch(void* const* d_in, const int* in_sizes, int n_in,
                              void* d_out, int out_size)
{
    const float* x      = (const float*)d_in[0];
    const float* ln1_g  = (const float*)d_in[1];
    const float* ln1_b  = (const float*)d_in[2];
    const float* w_attn = (const float*)d_in[3];
    const float* b_attn = (const float*)d_in[4];
    const float* w_proj = (const float*)d_in[5];
    const float* b_proj = (const float*)d_in[6];
    const float* ln2_g  = (const float*)d_in[7];
    const float* ln2_b  = (const float*)d_in[8];
    const float* w_fc   = (const float*)d_in[9];
    const float* b_fc   = (const float*)d_in[10];
    const float* w_fc2  = (const float*)d_in[11];
    const float* b_fc2  = (const float*)d_in[12];
    float* out = (float*)d_out;

    float *x2;
    __half *h, *y, *f;
    __half *wa, *wp, *wf, *w2;
    __half *aq, *ak, *av;
    cudaGetSymbolAddress((void**)&x2,  g_x2);
    cudaGetSymbolAddress((void**)&h,   g_h);
    cudaGetSymbolAddress((void**)&y,   g_y);
    cudaGetSymbolAddress((void**)&f,   g_f);
    cudaGetSymbolAddress((void**)&wa,  g_wa);
    cudaGetSymbolAddress((void**)&wp,  g_wp);
    cudaGetSymbolAddress((void**)&wf,  g_wf);
    cudaGetSymbolAddress((void**)&w2,  g_w2);
    cudaGetSymbolAddress((void**)&aq,  g_aq);
    cudaGetSymbolAddress((void**)&ak,  g_ak);
    cudaGetSymbolAddress((void**)&av,  g_av);

    cudaFuncSetAttribute(gemm_f16<1>, cudaFuncAttributeMaxDynamicSharedMemorySize, SMEM_GEMM);
    cudaFuncSetAttribute(gemm_f16<2>, cudaFuncAttributeMaxDynamicSharedMemorySize, SMEM_GEMM);
    cudaFuncSetAttribute(gemm_f16<3>, cudaFuncAttributeMaxDynamicSharedMemorySize, SMEM_GEMM);
    cudaFuncSetAttribute(attn_mma_kernel, cudaFuncAttributeMaxDynamicSharedMemorySize, ATT_SMEM);

    dim3 blk(256);

    wconv_kernel<<<dim3(3*CEMB/32, CEMB/32), blk>>>(w_attn, wa, CEMB, 3*CEMB);
    wconv_kernel<<<dim3(CEMB/32,   CEMB/32), blk>>>(w_proj, wp, CEMB, CEMB);
    wconv_kernel<<<dim3(DFF/32,    CEMB/32), blk>>>(w_fc,   wf, CEMB, DFF);
    wconv_kernel<<<dim3(CEMB/32,   DFF/32),  blk>>>(w_fc2,  w2, DFF,  CEMB);

    ln_kernel<<<MROWS, blk>>>(x, ln1_g, ln1_b, h);
    // fused QKV: writes q(scaled)/k/v fp16 [bh][t][d] directly
    gemm_f16<3><<<dim3(3*CEMB/BN, MROWS/BM), GT, SMEM_GEMM>>>(
        h, wa, b_attn, nullptr, nullptr, nullptr, aq, ak, av, MROWS, 3*CEMB, CEMB);
    attn_mma_kernel<<<dim3(TT/128, BB*NHEADS), blk, ATT_SMEM>>>(aq, ak, av, y);
    gemm_f16<1><<<dim3(CEMB/BN, MROWS/BM), GT, SMEM_GEMM>>>(
        y, wp, b_proj, x, x2, nullptr, nullptr, nullptr, nullptr, MROWS, CEMB, CEMB);
    ln_kernel<<<MROWS, blk>>>(x2, ln2_g, ln2_b, h);
    gemm_f16<2><<<dim3(DFF/BN, MROWS/BM), GT, SMEM_GEMM>>>(
        h, wf, b_fc, nullptr, nullptr, f, nullptr, nullptr, nullptr, MROWS, DFF, CEMB);
    gemm_f16<1><<<dim3(CEMB/BN, MROWS/BM), GT, SMEM_GEMM>>>(
        f, w2, b_fc2, x2, out, nullptr, nullptr, nullptr, nullptr, MROWS, CEMB, DFF);
}

// round 8
// speedup vs baseline: 1.4689x; 1.4689x over previous
#include <cuda_runtime.h>
#include <cuda_fp16.h>
#include <math.h>
#include <stdint.h>

#define CEMB 1024
#define NHEADS 16
#define HS 64
#define DFF 4096
#define BB 4
#define TT 2048
#define MROWS (BB*TT)   // 8192

#define BM 128
#define BN 128
#define BKE 64
#define GT 256

// ---------------- scratch ----------------
__device__ float g_qkv[(size_t)MROWS * 3 * CEMB];
__device__ float g_x2 [(size_t)MROWS * CEMB];
__device__ __half g_h [(size_t)MROWS * CEMB];       // ln out
__device__ __half g_y [(size_t)MROWS * CEMB];       // attn out
__device__ __half g_f [(size_t)MROWS * DFF];        // mlp hidden
// weights, transposed to [N,K] K-major, fp16
__device__ __half g_wa[(size_t)3*CEMB * CEMB];
__device__ __half g_wp[(size_t)CEMB * CEMB];
__device__ __half g_wf[(size_t)DFF * CEMB];
__device__ __half g_w2[(size_t)CEMB * DFF];
// attention operands
__device__ __half g_aq[(size_t)64 * TT * HS];
__device__ __half g_ak[(size_t)64 * TT * HS];
__device__ __half g_av[(size_t)64 * HS * TT];       // V transposed [bh][d][t]

// ---------------- PTX helpers ----------------
__device__ __forceinline__ uint32_t smem_u32(const void* p) {
    uint32_t a;
    asm("{ .reg .u64 t; cvta.to.shared.u64 t, %1; cvt.u32.u64 %0, t; }" : "=r"(a) : "l"(p));
    return a;
}
#define CP_ASYNC16(s, g) \
    asm volatile("cp.async.cg.shared.global [%0], [%1], 16;" :: "r"(s), "l"(g) : "memory")
#define CP_COMMIT() asm volatile("cp.async.commit_group;" ::: "memory")
#define CP_WAIT1()  asm volatile("cp.async.wait_group 1;" ::: "memory")
#define CP_WAIT0()  asm volatile("cp.async.wait_group 0;" ::: "memory")
#define LDSM_X4(r0, r1, r2, r3, addr) \
    asm volatile("ldmatrix.sync.aligned.m8n8.x4.shared.b16 {%0,%1,%2,%3}, [%4];" \
        : "=r"(r0), "=r"(r1), "=r"(r2), "=r"(r3) : "r"(addr))
#define MMAF16(c, a, b0v, b1v) \
    asm volatile("mma.sync.aligned.m16n8k16.row.col.f32.f16.f16.f32 " \
        "{%0,%1,%2,%3}, {%4,%5,%6,%7}, {%8,%9}, {%0,%1,%2,%3};" \
        : "+f"((c)[0]), "+f"((c)[1]), "+f"((c)[2]), "+f"((c)[3]) \
        : "r"((a)[0]), "r"((a)[1]), "r"((a)[2]), "r"((a)[3]), "r"(b0v), "r"(b1v))
#define STS32(addr, v) \
    asm volatile("st.shared.b32 [%0], %1;" :: "r"(addr), "r"(v) : "memory")

__device__ __forceinline__ uint32_t sw128(uint32_t off) { return off ^ ((off >> 3) & 0x70); }

__device__ __forceinline__ float gelu_f(float x) {
    float t = tanhf(0.79788456080286536f * (x + 0.044715f * x * x * x));
    return 0.5f * x * (1.0f + t);
}

union H4 { __half h[4]; uint2 u; };
union H2 { __half h[2]; uint32_t u; };

// ---------------- weight transpose + fp16 convert ----------------
__global__ __launch_bounds__(256) void wconv_kernel(const float* __restrict__ W,
    __half* __restrict__ Wf, int K, int N)
{
    __shared__ float t[32][33];
    int n0 = blockIdx.x * 32, k0 = blockIdx.y * 32;
    int tx = threadIdx.x & 31, ty = threadIdx.x >> 5;
    #pragma unroll
    for (int r = ty; r < 32; r += 8)
        t[r][tx] = W[(size_t)(k0 + r) * N + n0 + tx];
    __syncthreads();
    #pragma unroll
    for (int r = ty; r < 32; r += 8)
        Wf[(size_t)(n0 + r) * K + k0 + tx] = __float2half(t[tx][r]);
}

// ---------------- LayerNorm -> fp16 ----------------
__global__ __launch_bounds__(256) void ln_kernel(const float* __restrict__ x,
                                                 const float* __restrict__ g,
                                                 const float* __restrict__ b,
                                                 __half* __restrict__ oh)
{
    int row = blockIdx.x;
    int t = threadIdx.x;
    float4 v = ((const float4*)(x + (size_t)row * CEMB))[t];
    float s  = v.x + v.y + v.z + v.w;
    float ss = v.x*v.x + v.y*v.y + v.z*v.z + v.w*v.w;
    #pragma unroll
    for (int o = 16; o > 0; o >>= 1) {
        s  += __shfl_xor_sync(0xffffffffu, s,  o);
        ss += __shfl_xor_sync(0xffffffffu, ss, o);
    }
    __shared__ float red[16];
    int warp = t >> 5, lane = t & 31;
    if (lane == 0) { red[warp] = s; red[warp + 8] = ss; }
    __syncthreads();
    float sum = 0.f, sumsq = 0.f;
    #pragma unroll
    for (int w = 0; w < 8; w++) { sum += red[w]; sumsq += red[w + 8]; }
    float mu   = sum * (1.0f / CEMB);
    float var  = sumsq * (1.0f / CEMB) - mu * mu;
    float rstd = rsqrtf(var + 1e-5f);
    float4 gv = ((const float4*)g)[t];
    float4 bv = ((const float4*)b)[t];
    H4 o;
    o.h[0] = __float2half((v.x - mu) * rstd * gv.x + bv.x);
    o.h[1] = __float2half((v.y - mu) * rstd * gv.y + bv.y);
    o.h[2] = __float2half((v.z - mu) * rstd * gv.z + bv.z);
    o.h[3] = __float2half((v.w - mu) * rstd * gv.w + bv.w);
    *(uint2*)(oh + (size_t)row * CEMB + t * 4) = o.u;
}

// ---------------- HMMA fp16 GEMM: C = A @ B^T + bias ----------------
// 3-stage cp.async pipeline, one __syncthreads per k-iter.
// stage: A 16K | B 16K = 32KB; 3 stages = 96KB, 2 CTAs/SM.
#define STAGE_BYTES 32768
#define SMEM_GEMM (3 * STAGE_BYTES + 1024)

template<int EPI>
__global__ __launch_bounds__(GT, 2) void gemm_f16(
    const __half* __restrict__ Ah,
    const __half* __restrict__ Bf,
    const float* __restrict__ bias, const float* __restrict__ R,
    float* __restrict__ Cf, __half* __restrict__ Ch,
    int M, int N, int K)
{
    extern __shared__ char dsm[];
    uintptr_t pa = ((uintptr_t)dsm + 1023) & ~(uintptr_t)1023;
    uint32_t sb = smem_u32((char*)pa);

    int tid = threadIdx.x;
    int wid = tid >> 5, lid = tid & 31;
    int wm = wid >> 1, wn = wid & 1;
    int m0 = blockIdx.y * BM, n0 = blockIdx.x * BN;

    const int NC = K / BKE;
    int lrow = tid >> 3;
    int lch  = tid & 7;

    auto load_stage = [&](int c, int buf) {
        uint32_t st = sb + buf * STAGE_BYTES;
        int k0 = c * BKE;
        #pragma unroll
        for (int t = 0; t < 4; t++) {
            int row = lrow + t * 32;
            uint32_t so = sw128((uint32_t)(row * 128 + lch * 16));
            size_t ga = (size_t)(m0 + row) * K + k0 + lch * 8;
            CP_ASYNC16(st + so,         (const char*)(Ah + ga));
            size_t gb = (size_t)(n0 + row) * K + k0 + lch * 8;
            CP_ASYNC16(st + 16384 + so, (const char*)(Bf + gb));
        }
    };

    float acc[2][8][4];
    #pragma unroll
    for (int mi = 0; mi < 2; mi++)
        #pragma unroll
        for (int j = 0; j < 8; j++)
            #pragma unroll
            for (int q = 0; q < 4; q++) acc[mi][j][q] = 0.f;

    int lrow16 = lid & 15;
    int khalf  = lid >> 4;

    load_stage(0, 0); CP_COMMIT();
    load_stage(1, 1); CP_COMMIT();

    int rbuf = 0, wbuf = 2;
    for (int c = 0; c < NC; c++) {
        if (c + 2 < NC) { CP_WAIT1(); } else { CP_WAIT0(); }
        __syncthreads();
        if (c + 2 < NC) {
            load_stage(c + 2, wbuf); CP_COMMIT();
            wbuf = (wbuf == 2) ? 0 : wbuf + 1;
        }

        uint32_t st = sb + rbuf * STAGE_BYTES;
        rbuf = (rbuf == 2) ? 0 : rbuf + 1;

        #pragma unroll
        for (int s = 0; s < 4; s++) {
            uint32_t aH[2][4], bH[4][4];
            #pragma unroll
            for (int mi = 0; mi < 2; mi++) {
                int row = wm * 32 + mi * 16 + lrow16;
                int ch = (s * 2 + khalf) ^ (row & 7);
                uint32_t ad = st + (uint32_t)(row * 128 + ch * 16);
                LDSM_X4(aH[mi][0], aH[mi][1], aH[mi][2], aH[mi][3], ad);
            }
            #pragma unroll
            for (int nb = 0; nb < 4; nb++) {
                int row = wn * 64 + nb * 16 + lrow16;
                int ch = (s * 2 + khalf) ^ (row & 7);
                uint32_t bd = st + 16384 + (uint32_t)(row * 128 + ch * 16);
                LDSM_X4(bH[nb][0], bH[nb][1], bH[nb][2], bH[nb][3], bd);
            }
            #pragma unroll
            for (int mi = 0; mi < 2; mi++) {
                #pragma unroll
                for (int nb = 0; nb < 4; nb++) {
                    MMAF16(acc[mi][nb*2],   aH[mi], bH[nb][0], bH[nb][2]);
                    MMAF16(acc[mi][nb*2+1], aH[mi], bH[nb][1], bH[nb][3]);
                }
            }
        }
    }

    int gid = lid >> 2, tig = lid & 3;
    #pragma unroll
    for (int mi = 0; mi < 2; mi++) {
        #pragma unroll
        for (int j = 0; j < 8; j++) {
            int r0 = m0 + wm * 32 + mi * 16 + gid;
            int r1 = r0 + 8;
            int col = n0 + wn * 64 + j * 8 + tig * 2;
            float b0 = bias[col], b1 = bias[col + 1];
            float v0 = acc[mi][j][0] + b0, v1 = acc[mi][j][1] + b1;
            float v2 = acc[mi][j][2] + b0, v3 = acc[mi][j][3] + b1;
            if (EPI == 1) {
                float2 q0 = *(const float2*)(R + (size_t)r0 * N + col);
                float2 q1 = *(const float2*)(R + (size_t)r1 * N + col);
                v0 += q0.x; v1 += q0.y; v2 += q1.x; v3 += q1.y;
            }
            if (EPI == 2) {
                v0 = gelu_f(v0); v1 = gelu_f(v1); v2 = gelu_f(v2); v3 = gelu_f(v3);
                H2 h0, h1;
                h0.h[0] = __float2half(v0); h0.h[1] = __float2half(v1);
                h1.h[0] = __float2half(v2); h1.h[1] = __float2half(v3);
                *(uint32_t*)(Ch + (size_t)r0 * N + col) = h0.u;
                *(uint32_t*)(Ch + (size_t)r1 * N + col) = h1.u;
            } else {
                *(float2*)(Cf + (size_t)r0 * N + col) = make_float2(v0, v1);
                *(float2*)(Cf + (size_t)r1 * N + col) = make_float2(v2, v3);
            }
        }
    }
}

// ---------------- attention prep ----------------
__global__ __launch_bounds__(256) void attnprep_kernel(
    const float* __restrict__ qkv,
    __half* __restrict__ Qf, __half* __restrict__ Kf, __half* __restrict__ Vt)
{
    __shared__ float vs[64][65];
    int tb = blockIdx.x, bh = blockIdx.y;
    int b = bh >> 4, hd = bh & 15;
    int t0 = tb * 64;
    int tid = threadIdx.x;

    for (int i = tid; i < 1024; i += 256) {
        int r = i >> 4, c4 = (i & 15) * 4;
        const float* base = qkv + ((size_t)(b * TT + t0 + r)) * (3 * CEMB) + hd * HS + c4;
        float4 q = *(const float4*)base;
        float4 k = *(const float4*)(base + CEMB);
        float4 v = *(const float4*)(base + 2 * CEMB);
        H4 qq, kk;
        qq.h[0] = __float2half(q.x * 0.125f); qq.h[1] = __float2half(q.y * 0.125f);
        qq.h[2] = __float2half(q.z * 0.125f); qq.h[3] = __float2half(q.w * 0.125f);
        kk.h[0] = __float2half(k.x); kk.h[1] = __float2half(k.y);
        kk.h[2] = __float2half(k.z); kk.h[3] = __float2half(k.w);
        size_t qo = ((size_t)bh * TT + t0 + r) * HS + c4;
        *(uint2*)(Qf + qo) = qq.u;
        *(uint2*)(Kf + qo) = kk.u;
        vs[r][c4] = v.x; vs[r][c4+1] = v.y; vs[r][c4+2] = v.z; vs[r][c4+3] = v.w;
    }
    __syncthreads();
    for (int i = tid; i < 1024; i += 256) {
        int d = i >> 4, tq = (i & 15) * 4;
        H4 vv;
        vv.h[0] = __float2half(vs[tq+0][d]);
        vv.h[1] = __float2half(vs[tq+1][d]);
        vv.h[2] = __float2half(vs[tq+2][d]);
        vv.h[3] = __float2half(vs[tq+3][d]);
        size_t vo = ((size_t)bh * HS + d) * TT + t0 + tq;
        *(uint2*)(Vt + vo) = vv.u;
    }
}

// ---------------- HMMA flash attention (all fp16, 3-stage KV pipeline) ----------------
// smem: Q 16K @0 | KV buf(b) @16K+16K*b (b=0..2): K 8K, Vt 8K | P 16K @64K = 80KB
#define ATSM_BUF(b) (16384 + (b) * 16384)
#define ATSM_P 65536
#define ATT_SMEM (81920 + 1024)

__global__ __launch_bounds__(256, 2) void attn_mma_kernel(
    const __half* __restrict__ Qf_, const __half* __restrict__ Kf_,
    const __half* __restrict__ Vt_,
    __half* __restrict__ yo)
{
    extern __shared__ char dsm[];
    uintptr_t pa = ((uintptr_t)dsm + 1023) & ~(uintptr_t)1023;
    uint32_t sb = smem_u32((char*)pa);

    int qt = gridDim.x - 1 - blockIdx.x;
    int q0 = qt * 128;
    int bh = blockIdx.y;
    int b = bh >> 4, hd = bh & 15;
    size_t hq = (size_t)bh * TT * HS;

    int tid = threadIdx.x;
    int wid = tid >> 5, lid = tid & 31;
    int lrow16 = lid & 15, khalf = lid >> 4;
    int arow = wid * 16 + lrow16;

    auto load_kv = [&](int jb, int buf) {
        int j0 = jb * 64;
        uint32_t st = sb + ATSM_BUF(buf);
        const char* kf = (const char*)(Kf_ + hq + (size_t)j0 * HS);
        const char* vt = (const char*)(Vt_ + hq) + (size_t)j0 * 2;
        #pragma unroll
        for (int i = tid; i < 512; i += 256) {
            int row = i >> 3, ch = i & 7;
            uint32_t so = sw128((uint32_t)(row * 128 + ch * 16));
            CP_ASYNC16(st + so,        kf + row * 128 + ch * 16);
            CP_ASYNC16(st + 8192 + so, vt + (size_t)row * (TT * 2) + ch * 16);
        }
    };

    {
        const char* qf = (const char*)(Qf_ + hq + (size_t)q0 * HS);
        #pragma unroll
        for (int i = tid; i < 1024; i += 256) {
            int row = i >> 3, ch = i & 7;
            uint32_t so = sw128((uint32_t)(row * 128 + ch * 16));
            CP_ASYNC16(sb + so, qf + row * 128 + ch * 16);
        }
    }
    load_kv(0, 0); CP_COMMIT();   // group: Q + KV0
    load_kv(1, 1); CP_COMMIT();   // group: KV1

    float m_[2] = {-INFINITY, -INFINITY};
    float l_[2] = {0.f, 0.f};
    float acc[8][4];
    #pragma unroll
    for (int nb = 0; nb < 8; nb++)
        #pragma unroll
        for (int q = 0; q < 4; q++) acc[nb][q] = 0.f;

    int jbmax = q0 / 64 + 1;
    int rbuf = 0, wbuf = 2;
    for (int jb = 0; jb <= jbmax; jb++) {
        if (jb + 2 <= jbmax) { CP_WAIT1(); } else { CP_WAIT0(); }
        __syncthreads();
        if (jb + 2 <= jbmax) {
            load_kv(jb + 2, wbuf); CP_COMMIT();
            wbuf = (wbuf == 2) ? 0 : wbuf + 1;
        }

        uint32_t sK = sb + ATSM_BUF(rbuf);
        uint32_t sV = sK + 8192;
        rbuf = (rbuf == 2) ? 0 : rbuf + 1;

        float s[8][4];
        #pragma unroll
        for (int nb = 0; nb < 8; nb++)
            #pragma unroll
            for (int q = 0; q < 4; q++) s[nb][q] = 0.f;

        #pragma unroll
        for (int ks = 0; ks < 4; ks++) {
            int ach = (ks * 2 + khalf) ^ (arow & 7);
            uint32_t aa = sb + (uint32_t)(arow * 128 + ach * 16);
            uint32_t aH[4];
            LDSM_X4(aH[0], aH[1], aH[2], aH[3], aa);
            uint32_t bH[4][4];
            #pragma unroll
            for (int nb2 = 0; nb2 < 4; nb2++) {
                int br = nb2 * 16 + lrow16;
                int bch = (ks * 2 + khalf) ^ (br & 7);
                uint32_t ba = sK + (uint32_t)(br * 128 + bch * 16);
                LDSM_X4(bH[nb2][0], bH[nb2][1], bH[nb2][2], bH[nb2][3], ba);
            }
            #pragma unroll
            for (int nb2 = 0; nb2 < 4; nb2++) {
                MMAF16(s[nb2*2],   aH, bH[nb2][0], bH[nb2][2]);
                MMAF16(s[nb2*2+1], aH, bH[nb2][1], bH[nb2][3]);
            }
        }

        int j0 = jb * 64;
        if (j0 + 63 > q0 + wid * 16) {
            int r0g = q0 + wid * 16 + (lid >> 2);
            #pragma unroll
            for (int nb = 0; nb < 8; nb++) {
                int c0 = j0 + nb * 8 + (lid & 3) * 2;
                if (c0     > r0g)     s[nb][0] = -INFINITY;
                if (c0 + 1 > r0g)     s[nb][1] = -INFINITY;
                if (c0     > r0g + 8) s[nb][2] = -INFINITY;
                if (c0 + 1 > r0g + 8) s[nb][3] = -INFINITY;
            }
        }

        float rmax[2] = {-INFINITY, -INFINITY};
        #pragma unroll
        for (int nb = 0; nb < 8; nb++) {
            rmax[0] = fmaxf(rmax[0], fmaxf(s[nb][0], s[nb][1]));
            rmax[1] = fmaxf(rmax[1], fmaxf(s[nb][2], s[nb][3]));
        }
        #pragma unroll
        for (int o = 1; o <= 2; o <<= 1) {
            rmax[0] = fmaxf(rmax[0], __shfl_xor_sync(0xffffffffu, rmax[0], o));
            rmax[1] = fmaxf(rmax[1], __shfl_xor_sync(0xffffffffu, rmax[1], o));
        }
        float mn0 = fmaxf(m_[0], rmax[0]);
        float mn1 = fmaxf(m_[1], rmax[1]);
        float alpha0 = __expf(m_[0] - mn0);
        float alpha1 = __expf(m_[1] - mn1);
        m_[0] = mn0; m_[1] = mn1;
        float rs[2] = {0.f, 0.f};
        #pragma unroll
        for (int nb = 0; nb < 8; nb++) {
            s[nb][0] = __expf(s[nb][0] - mn0); rs[0] += s[nb][0];
            s[nb][1] = __expf(s[nb][1] - mn0); rs[0] += s[nb][1];
            s[nb][2] = __expf(s[nb][2] - mn1); rs[1] += s[nb][2];
            s[nb][3] = __expf(s[nb][3] - mn1); rs[1] += s[nb][3];
        }
        #pragma unroll
        for (int o = 1; o <= 2; o <<= 1) {
            rs[0] += __shfl_xor_sync(0xffffffffu, rs[0], o);
            rs[1] += __shfl_xor_sync(0xffffffffu, rs[1], o);
        }
        l_[0] = l_[0] * alpha0 + rs[0];
        l_[1] = l_[1] * alpha1 + rs[1];
        #pragma unroll
        for (int nb = 0; nb < 8; nb++) {
            acc[nb][0] *= alpha0; acc[nb][1] *= alpha0;
            acc[nb][2] *= alpha1; acc[nb][3] *= alpha1;
        }

        {
            int r0 = wid * 16 + (lid >> 2);
            #pragma unroll
            for (int nb = 0; nb < 8; nb++) {
                int coff = (nb * 8 + (lid & 3) * 2) * 2;
                uint32_t o0 = sw128((uint32_t)(r0 * 128 + coff));
                uint32_t o1 = sw128((uint32_t)((r0 + 8) * 128 + coff));
                H2 h;
                h.h[0] = __float2half(s[nb][0]); h.h[1] = __float2half(s[nb][1]);
                STS32(sb + ATSM_P + o0, h.u);
                h.h[0] = __float2half(s[nb][2]); h.h[1] = __float2half(s[nb][3]);
                STS32(sb + ATSM_P + o1, h.u);
            }
        }
        __syncwarp();

        #pragma unroll
        for (int ks = 0; ks < 4; ks++) {
            int ach = (ks * 2 + khalf) ^ (arow & 7);
            uint32_t paddr = sb + ATSM_P + (uint32_t)(arow * 128 + ach * 16);
            uint32_t pH[4];
            LDSM_X4(pH[0], pH[1], pH[2], pH[3], paddr);
            uint32_t bH[4][4];
            #pragma unroll
            for (int nb2 = 0; nb2 < 4; nb2++) {
                int br = nb2 * 16 + lrow16;
                int bch = (ks * 2 + khalf) ^ (br & 7);
                uint32_t ba = sV + (uint32_t)(br * 128 + bch * 16);
                LDSM_X4(bH[nb2][0], bH[nb2][1], bH[nb2][2], bH[nb2][3], ba);
            }
            #pragma unroll
            for (int nb2 = 0; nb2 < 4; nb2++) {
                MMAF16(acc[nb2*2],   pH, bH[nb2][0], bH[nb2][2]);
                MMAF16(acc[nb2*2+1], pH, bH[nb2][1], bH[nb2][3]);
            }
        }
    }

    float inv0 = 1.0f / l_[0];
    float inv1 = 1.0f / l_[1];
    size_t r0g = (size_t)b * TT + q0 + wid * 16 + (lid >> 2);
    #pragma unroll
    for (int nb = 0; nb < 8; nb++) {
        int col = hd * HS + nb * 8 + (lid & 3) * 2;
        H2 h;
        h.h[0] = __float2half(acc[nb][0] * inv0);
        h.h[1] = __float2half(acc[nb][1] * inv0);
        *(uint32_t*)(yo + r0g * CEMB + col) = h.u;
        h.h[0] = __float2half(acc[nb][2] * inv1);
        h.h[1] = __float2half(acc[nb][3] * inv1);
        *(uint32_t*)(yo + (r0g + 8) * CEMB + col) = h.u;
    }
}

// ---------------- launch ----------------
extern "C" void kernel_launch(void* const* d_in, const int* in_sizes, int n_in,
                              void* d_out, int out_size)
{
    const float* x      = (const float*)d_in[0];
    const float* ln1_g  = (const float*)d_in[1];
    const float* ln1_b  = (const float*)d_in[2];
    const float* w_attn = (const float*)d_in[3];
    const float* b_attn = (const float*)d_in[4];
    const float* w_proj = (const float*)d_in[5];
    const float* b_proj = (const float*)d_in[6];
    const float* ln2_g  = (const float*)d_in[7];
    const float* ln2_b  = (const float*)d_in[8];
    const float* w_fc   = (const float*)d_in[9];
    const float* b_fc   = (const float*)d_in[10];
    const float* w_fc2  = (const float*)d_in[11];
    const float* b_fc2  = (const float*)d_in[12];
    float* out = (float*)d_out;

    float *qkv, *x2;
    __half *h, *y, *f;
    __half *wa, *wp, *wf, *w2;
    __half *aq, *ak, *av;
    cudaGetSymbolAddress((void**)&qkv, g_qkv);
    cudaGetSymbolAddress((void**)&x2,  g_x2);
    cudaGetSymbolAddress((void**)&h,   g_h);
    cudaGetSymbolAddress((void**)&y,   g_y);
    cudaGetSymbolAddress((void**)&f,   g_f);
    cudaGetSymbolAddress((void**)&wa,  g_wa);
    cudaGetSymbolAddress((void**)&wp,  g_wp);
    cudaGetSymbolAddress((void**)&wf,  g_wf);
    cudaGetSymbolAddress((void**)&w2,  g_w2);
    cudaGetSymbolAddress((void**)&aq,  g_aq);
    cudaGetSymbolAddress((void**)&ak,  g_ak);
    cudaGetSymbolAddress((void**)&av,  g_av);

    cudaFuncSetAttribute(gemm_f16<0>, cudaFuncAttributeMaxDynamicSharedMemorySize, SMEM_GEMM);
    cudaFuncSetAttribute(gemm_f16<1>, cudaFuncAttributeMaxDynamicSharedMemorySize, SMEM_GEMM);
    cudaFuncSetAttribute(gemm_f16<2>, cudaFuncAttributeMaxDynamicSharedMemorySize, SMEM_GEMM);
    cudaFuncSetAttribute(attn_mma_kernel, cudaFuncAttributeMaxDynamicSharedMemorySize, ATT_SMEM);

    dim3 blk(256);

    wconv_kernel<<<dim3(3*CEMB/32, CEMB/32), blk>>>(w_attn, wa, CEMB, 3*CEMB);
    wconv_kernel<<<dim3(CEMB/32,   CEMB/32), blk>>>(w_proj, wp, CEMB, CEMB);
    wconv_kernel<<<dim3(DFF/32,    CEMB/32), blk>>>(w_fc,   wf, CEMB, DFF);
    wconv_kernel<<<dim3(CEMB/32,   DFF/32),  blk>>>(w_fc2,  w2, DFF,  CEMB);

    ln_kernel<<<MROWS, blk>>>(x, ln1_g, ln1_b, h);
    gemm_f16<0><<<dim3(3*CEMB/BN, MROWS/BM), GT, SMEM_GEMM>>>(
        h, wa, b_attn, nullptr, qkv, nullptr, MROWS, 3*CEMB, CEMB);
    attnprep_kernel<<<dim3(TT/64, BB*NHEADS), blk>>>(qkv, aq, ak, av);
    attn_mma_kernel<<<dim3(TT/128, BB*NHEADS), blk, ATT_SMEM>>>(aq, ak, av, y);
    gemm_f16<1><<<dim3(CEMB/BN, MROWS/BM), GT, SMEM_GEMM>>>(
        y, wp, b_proj, x, x2, nullptr, MROWS, CEMB, CEMB);
    ln_kernel<<<MROWS, blk>>>(x2, ln2_g, ln2_b, h);
    gemm_f16<2><<<dim3(DFF/BN, MROWS/BM), GT, SMEM_GEMM>>>(
        h, wf, b_fc, nullptr, nullptr, f, MROWS, DFF, CEMB);
    gemm_f16<1><<<dim3(CEMB/BN, MROWS/BM), GT, SMEM_GEMM>>>(
        f, w2, b_fc2, x2, out, nullptr, MROWS, CEMB, DFF);
}